// round 13
// baseline (speedup 1.0000x reference)
#include <cuda_runtime.h>
#include <cstdint>

#define NB   8
#define CIN  64
#define COUT 128
#define HH   32
#define WW   32
#define QWN  (COUT*144)            // 18432 int32 words of packed B

#define BROW   592                 // 576+16 pad (37*16B, odd) -> conflict-free ldmatrix
#define BOFF   0
#define BSZ    (COUT*BROW)         // 75776
#define HALO   BSZ                 // float halo: 136 pixels x 65 floats (odd stride)
#define HSTR   65
#define HALOF  (136*HSTR)          // 8840 floats
#define STAGE  (HALO + HALOF*4)    // 111136: int8 staging, 136 pixels x 80B
#define PIXSTR 80
#define WROW   (STAGE + 136*PIXSTR)// 122016: w-row floats (576)
#define SMEM_SZ (WROW + 576*4)     // 124320

#define NCTA 128
#define NTHR 512

// ---------------- scratch (device globals; no allocation) ----------------
__device__ unsigned g_partx[NCTA];
__device__ unsigned g_partw[NCTA];
__device__ int      g_wpack[QWN];          // [co][tap][c4w]; CTA bx packs row co=bx
__device__ unsigned g_flagX[NCTA];         // monotonic per-CTA barrier flags
__device__ unsigned g_flagW[NCTA];
__device__ unsigned g_flagB[NCTA];

__device__ __forceinline__ uint32_t smem_u32(const void* p) {
    uint32_t a;
    asm("{ .reg .u64 t; cvta.to.shared.u64 t, %1; cvt.u32.u64 %0, t; }" : "=r"(a) : "l"(p));
    return a;
}

#define LDSM_X4(r0, r1, r2, r3, a) \
    asm volatile("ldmatrix.sync.aligned.m8n8.x4.shared.b16 {%0,%1,%2,%3}, [%4];" \
                 : "=r"(r0), "=r"(r1), "=r"(r2), "=r"(r3) : "r"(a))

#define IMMA(c, a0, a1, a2, a3, b0, b1) \
    asm volatile("mma.sync.aligned.m16n8k32.row.col.s32.s8.s8.s32 " \
                 "{%0,%1,%2,%3}, {%4,%5,%6,%7}, {%8,%9}, {%0,%1,%2,%3};" \
                 : "+r"((c)[0]), "+r"((c)[1]), "+r"((c)[2]), "+r"((c)[3]) \
                 : "r"(a0), "r"(a1), "r"(a2), "r"(a3), "r"(b0), "r"(b1))

#define GBAR(id, n) asm volatile("bar.sync %0, %1;" :: "r"(id), "r"(n) : "memory")

__device__ __forceinline__ int quant(float v, float s) {
    float r = rintf(__fmul_rn(v, s));      // round half-to-even == jnp.round
    r = fminf(fmaxf(r, -128.0f), 127.0f);
    return (int)r;
}

// warp-cooperative grid barrier: parallel flag stores + cooperative poll.
// 128 CTAs all co-resident (1 CTA/SM). Monotonic +1 per launch -> graph-safe.
__device__ __forceinline__ void wbar(unsigned* flags, int bx, int lane) {
    unsigned tgt = 0u;
    if (lane == 0) {
        unsigned cur;
        asm volatile("ld.relaxed.gpu.u32 %0, [%1];" : "=r"(cur) : "l"(flags + bx));
        tgt = cur + 1u;
        asm volatile("fence.acq_rel.gpu;" ::: "memory");          // release prior stores
        asm volatile("st.relaxed.gpu.u32 [%0], %1;" :: "l"(flags + bx), "r"(tgt) : "memory");
    }
    tgt = __shfl_sync(0xffffffffu, tgt, 0);
    const unsigned* p = flags + lane;
    bool done;
    do {
        unsigned v0, v1, v2, v3;
        asm volatile("ld.relaxed.gpu.u32 %0, [%1];" : "=r"(v0) : "l"(p));
        asm volatile("ld.relaxed.gpu.u32 %0, [%1];" : "=r"(v1) : "l"(p + 32));
        asm volatile("ld.relaxed.gpu.u32 %0, [%1];" : "=r"(v2) : "l"(p + 64));
        asm volatile("ld.relaxed.gpu.u32 %0, [%1];" : "=r"(v3) : "l"(p + 96));
        done = ((int)(v0 - tgt) >= 0) & ((int)(v1 - tgt) >= 0)
             & ((int)(v2 - tgt) >= 0) & ((int)(v3 - tgt) >= 0);
    } while (!__all_sync(0xffffffffu, done));
    asm volatile("fence.acq_rel.gpu;" ::: "memory");              // acquire
}

// ---------------- ONE fused kernel, dual warp-specialized pipelines ----------------
__global__ void __launch_bounds__(NTHR, 1)
k_fused(const float* __restrict__ x, const float* __restrict__ w,
        const float* __restrict__ bias,
        const float* __restrict__ Tf_in, const float* __restrict__ Tw_in,
        float* __restrict__ out) {
    extern __shared__ char sm[];
    __shared__ unsigned sredx[8], sredw[8];
    __shared__ float s_sc[3], s_T[2];

    const int t = threadIdx.x, wid = t >> 5, lane = t & 31;
    const int bx = blockIdx.x;
    const int b  = bx >> 4;
    const int y0 = (bx & 15) * 2;

    float* __restrict__ halo = (float*)(sm + HALO);
    float* __restrict__ wrow = (float*)(sm + WROW);

    if (wid < 8) {
        // ================= x-path: warps 0-7 (256 threads) =================
        // zero halo (covers padding rows/cols)
        {
            int4 z = make_int4(0, 0, 0, 0);
            int4* hz = (int4*)(sm + HALO);
            #pragma unroll
            for (int k = 0; k < 9; ++k) {
                int i = t + k*256;
                if (k < 8 || i < HALOF/4) hz[i] = z;
            }
        }
        GBAR(1, 256);
        // coalesced halo load: task j = (row4, ch); lane = col (one 128B line/iter)
        unsigned mx = 0u;
        #pragma unroll 8
        for (int j = wid; j < 256; j += 8) {
            int ch = j & 63, r4 = j >> 6;
            int R = y0 + r4;
            if (R >= 1 && R <= HH) {
                float v = x[((b*CIN + ch)*HH + (R - 1))*WW + lane];
                halo[(r4*34 + lane + 1)*HSTR + ch] = v;   // stride-65: conflict-free
                mx = max(mx, __float_as_uint(fabsf(v)));
            }
        }
        #pragma unroll
        for (int o = 16; o; o >>= 1) mx = max(mx, __shfl_xor_sync(0xffffffffu, mx, o));
        if (lane == 0) sredx[wid] = mx;
        GBAR(1, 256);
        if (wid == 0) {
            unsigned m2 = (lane < 8) ? sredx[lane] : 0u;
            #pragma unroll
            for (int o = 4; o; o >>= 1) m2 = max(m2, __shfl_xor_sync(0xffffffffu, m2, o));
            if (lane == 0) g_partx[bx] = m2;
            wbar(g_flagX, bx, lane);                       // cheap store/poll barrier
            unsigned vx = max(max(g_partx[lane], g_partx[lane + 32]),
                              max(g_partx[lane + 64], g_partx[lane + 96]));
            #pragma unroll
            for (int o = 16; o; o >>= 1) vx = max(vx, __shfl_xor_sync(0xffffffffu, vx, o));
            if (lane == 0) {
                float Tf = __fadd_rn(__fmul_rn(0.95f, Tf_in[0]),
                                     __fmul_rn(0.05f, __uint_as_float(vx)));
                s_T[0] = Tf;
                s_sc[0] = __fdiv_rn(127.0f, Tf);
            }
        }
        GBAR(1, 256);
        // quantize halo -> int8 staging (544 items = 136 pix x 4 c4-groups)
        {
            const float sf = s_sc[0];
            #pragma unroll
            for (int k = 0; k < 3; ++k) {
                int i = t + k*256;
                if (i < 544) {
                    int pix = i >> 2, c4 = i & 3;
                    const float* hp = halo + pix*HSTR + c4*16;
                    int q[16];
                    #pragma unroll
                    for (int j = 0; j < 16; ++j)
                        q[j] = quant(hp[j], sf) & 255;
                    int4 v;
                    v.x = q[0]  | (q[1]  << 8) | (q[2]  << 16) | (q[3]  << 24);
                    v.y = q[4]  | (q[5]  << 8) | (q[6]  << 16) | (q[7]  << 24);
                    v.z = q[8]  | (q[9]  << 8) | (q[10] << 16) | (q[11] << 24);
                    v.w = q[12] | (q[13] << 8) | (q[14] << 16) | (q[15] << 24);
                    *(int4*)(sm + STAGE + pix*PIXSTR + c4*16) = v;
                }
            }
        }
    } else {
        // ================= w-path: warps 8-15 (256 threads) =================
        const int tw = t - 256;
        unsigned mw;
        {
            float wv0 = w[bx*576 + tw];
            float wv1 = w[bx*576 + 256 + tw];
            wrow[tw] = wv0;
            wrow[256 + tw] = wv1;
            mw = max(__float_as_uint(fabsf(wv0)), __float_as_uint(fabsf(wv1)));
            if (tw < 64) {
                float wv2 = w[bx*576 + 512 + tw];
                wrow[512 + tw] = wv2;
                mw = max(mw, __float_as_uint(fabsf(wv2)));
            }
        }
        #pragma unroll
        for (int o = 16; o; o >>= 1) mw = max(mw, __shfl_xor_sync(0xffffffffu, mw, o));
        if (lane == 0) sredw[wid - 8] = mw;
        GBAR(2, 256);
        if (wid == 8) {
            unsigned m2 = (lane < 8) ? sredw[lane] : 0u;
            #pragma unroll
            for (int o = 4; o; o >>= 1) m2 = max(m2, __shfl_xor_sync(0xffffffffu, m2, o));
            if (lane == 0) g_partw[bx] = m2;
            wbar(g_flagW, bx, lane);
            unsigned vw = max(max(g_partw[lane], g_partw[lane + 32]),
                              max(g_partw[lane + 64], g_partw[lane + 96]));
            #pragma unroll
            for (int o = 16; o; o >>= 1) vw = max(vw, __shfl_xor_sync(0xffffffffu, vw, o));
            if (lane == 0) {
                float Tw = __fadd_rn(__fmul_rn(0.95f, Tw_in[0]),
                                     __fmul_rn(0.05f, __uint_as_float(vw)));
                s_T[1] = Tw;
                s_sc[1] = __fdiv_rn(127.0f, Tw);
            }
        }
        GBAR(2, 256);
        // pack OWN w row (144 words) from smem floats
        if (tw < 144) {
            const int tap = tw >> 4, c4w = tw & 15;
            const float sf = s_sc[1];
            int q0 = quant(wrow[(c4w*4 + 0)*9 + tap], sf) & 255;
            int q1 = quant(wrow[(c4w*4 + 1)*9 + tap], sf) & 255;
            int q2 = quant(wrow[(c4w*4 + 2)*9 + tap], sf) & 255;
            int q3 = quant(wrow[(c4w*4 + 3)*9 + tap], sf) & 255;
            g_wpack[bx*144 + tw] = q0 | (q1 << 8) | (q2 << 16) | (q3 << 24);
        }
        GBAR(2, 256);
        if (wid == 8) wbar(g_flagB, bx, lane);   // fence inside covers pack stores
        GBAR(2, 256);
        // B-fill: [co][576B] stride 592 (4608 int4 over 256 threads)
        {
            const int4* __restrict__ src = (const int4*)g_wpack;
            int4* __restrict__ Bm = (int4*)(sm + BOFF);
            #pragma unroll
            for (int k = 0; k < 18; ++k) {
                int i = tw + k*256;
                int co = i / 36, j = i % 36;
                Bm[co*37 + j] = src[i];
            }
        }
    }
    __syncthreads();
    if (t == 0)
        s_sc[2] = __fmul_rn(__fdiv_rn(s_T[0], 127.0f), __fdiv_rn(s_T[1], 127.0f));
    __syncthreads();

    // ===== mainloop: 16 warps = 4(M) x 4(N); warp = m16 x n32 =====
    const int wm = (wid & 3) * 16;
    const int wn = (wid >> 2) * 32;
    const uint32_t sbase = smem_u32(sm);

    const int pix = wm + (lane & 15);
    const uint32_t aAddr0 = sbase + STAGE
                          + (uint32_t)(((pix >> 5)*34 + (pix & 31))*PIXSTR)
                          + (uint32_t)(lane >> 4)*16;
    uint32_t bAddr[2];
    #pragma unroll
    for (int np = 0; np < 2; ++np)
        bAddr[np] = sbase + BOFF
                  + (uint32_t)(wn + np*16 + (lane & 7) + ((lane >> 4) & 1)*8)*BROW
                  + (uint32_t)((lane >> 3) & 1)*16;

    int acc[4][4];
    #pragma unroll
    for (int nf = 0; nf < 4; ++nf)
        #pragma unroll
        for (int j = 0; j < 4; ++j) acc[nf][j] = 0;

    #pragma unroll
    for (int ks = 0; ks < 18; ++ks) {
        const int tap = ks >> 1;
        const uint32_t aoff = (uint32_t)(((tap/3)*34 + (tap%3))*PIXSTR + (ks & 1)*32);
        const uint32_t boff = (uint32_t)ks * 32;
        uint32_t a[4], bb[2][4];
        LDSM_X4(a[0], a[1], a[2], a[3], aAddr0 + aoff);
        #pragma unroll
        for (int np = 0; np < 2; ++np)
            LDSM_X4(bb[np][0], bb[np][1], bb[np][2], bb[np][3], bAddr[np] + boff);
        #pragma unroll
        for (int nf = 0; nf < 4; ++nf)
            IMMA(acc[nf], a[0], a[1], a[2], a[3],
                 bb[nf >> 1][(nf & 1)*2], bb[nf >> 1][(nf & 1)*2 + 1]);
    }

    // ===== epilogue: s32 -> f32 * sc + bias =====
    const float sc = s_sc[2];
    const int p0 = wm + (lane >> 2);
    #pragma unroll
    for (int nf = 0; nf < 4; ++nf) {
        const int co0 = wn + nf*8 + (lane & 3)*2;
        const float b0 = __ldg(&bias[co0]);
        const float b1 = __ldg(&bias[co0 + 1]);
        #pragma unroll
        for (int half = 0; half < 2; ++half) {
            const int p = p0 + half*8;
            const int y = y0 + (p >> 5), xx = p & 31;
            float* po = out + (((size_t)b*COUT + co0)*HH + y)*WW + xx;
            po[0]     = (float)acc[nf][half*2]     * sc + b0;
            po[HH*WW] = (float)acc[nf][half*2 + 1] * sc + b1;
        }
    }
}

// ---------------- launch ----------------
extern "C" void kernel_launch(void* const* d_in, const int* in_sizes, int n_in,
                              void* d_out, int out_size) {
    const float* x    = (const float*)d_in[0];
    const float* w    = (const float*)d_in[1];
    const float* bias = (const float*)d_in[2];
    // d_in[3] = lut (exact a*b -> tensor core), d_in[4] = gradient_lut (unused)
    const float* Tf   = (const float*)d_in[5];
    const float* Tw   = (const float*)d_in[6];
    float* out = (float*)d_out;

    cudaFuncSetAttribute(k_fused, cudaFuncAttributeMaxDynamicSharedMemorySize, SMEM_SZ);
    k_fused<<<NCTA, NTHR, SMEM_SZ>>>(x, w, bias, Tf, Tw, out);
}

// round 14
// speedup vs baseline: 1.4314x; 1.4314x over previous
#include <cuda_runtime.h>
#include <cstdint>

#define NB   8
#define CIN  64
#define COUT 128
#define HH   32
#define WW   32
#define QWN  (COUT*144)            // 18432 int32 words of packed B

#define BROW   592                 // 576+16 pad (37*16B, odd) -> conflict-free ldmatrix
#define BOFF   0
#define BSZ    (COUT*BROW)         // 75776
#define HALO   BSZ                 // float halo: 136 pixels x 65 floats (odd stride)
#define HSTR   65
#define STAGE  (HALO + 136*HSTR*4) // 111136: int8 staging, 136 pixels x 80B
#define PIXSTR 80
#define WROW   (STAGE + 136*PIXSTR)// 122016: w-row floats (576)
#define SMEM_SZ (WROW + 576*4)     // 124320

#define NCTA 128
#define NTHR 512

// ---------------- scratch (device globals; no allocation) ----------------
__device__ unsigned g_partx[NCTA];
__device__ unsigned g_partw[NCTA];
__device__ int      g_wpack[QWN];         // [co][tap][c4w]; CTA bx packs row co=bx
__device__ unsigned g_barX = 0u;          // monotonic grid-barrier counters
__device__ unsigned g_barW = 0u;
__device__ unsigned g_barB = 0u;

__device__ __forceinline__ uint32_t smem_u32(const void* p) {
    uint32_t a;
    asm("{ .reg .u64 t; cvta.to.shared.u64 t, %1; cvt.u32.u64 %0, t; }" : "=r"(a) : "l"(p));
    return a;
}

#define LDSM_X4(r0, r1, r2, r3, a) \
    asm volatile("ldmatrix.sync.aligned.m8n8.x4.shared.b16 {%0,%1,%2,%3}, [%4];" \
                 : "=r"(r0), "=r"(r1), "=r"(r2), "=r"(r3) : "r"(a))

#define IMMA(c, a0, a1, a2, a3, b0, b1) \
    asm volatile("mma.sync.aligned.m16n8k32.row.col.s32.s8.s8.s32 " \
                 "{%0,%1,%2,%3}, {%4,%5,%6,%7}, {%8,%9}, {%0,%1,%2,%3};" \
                 : "+r"((c)[0]), "+r"((c)[1]), "+r"((c)[2]), "+r"((c)[3]) \
                 : "r"(a0), "r"(a1), "r"(a2), "r"(a3), "r"(b0), "r"(b1))

#define GBAR(id, n) asm volatile("bar.sync %0, %1;" :: "r"(id), "r"(n) : "memory")

__device__ __forceinline__ int quant(float v, float s) {
    float r = rintf(__fmul_rn(v, s));      // round half-to-even == jnp.round
    r = fminf(fmaxf(r, -128.0f), 127.0f);
    return (int)r;
}

// single-thread arrive+wait on a monotonic 128-CTA barrier (all CTAs co-resident)
__device__ __forceinline__ void bar_arrive_wait(unsigned* bar) {
    __threadfence();
    unsigned ticket = atomicAdd(bar, 1u);
    unsigned target = (ticket & ~127u) + 128u;
    unsigned v;
    do {
        asm volatile("ld.acquire.gpu.u32 %0, [%1];" : "=r"(v) : "l"(bar) : "memory");
    } while ((int)(v - target) < 0);
}

// ---------------- ONE fused kernel, dual warp-specialized pipelines ----------------
__global__ void __launch_bounds__(NTHR, 1)
k_fused(const float* __restrict__ x, const float* __restrict__ w,
        const float* __restrict__ bias,
        const float* __restrict__ Tf_in, const float* __restrict__ Tw_in,
        float* __restrict__ out) {
    extern __shared__ char sm[];
    __shared__ unsigned sredx[8], sredw[8];
    __shared__ float s_sc[3], s_T[2];

    const int t = threadIdx.x, wid = t >> 5, lane = t & 31;
    const int bx = blockIdx.x;
    const int b  = bx >> 4;
    const int y0 = (bx & 15) * 2;

    float* __restrict__ halo = (float*)(sm + HALO);
    float* __restrict__ wrow = (float*)(sm + WROW);

    if (wid < 8) {
        // ================= x-path: warps 0-7 (256 threads) =================
        unsigned mx = 0u;
        #pragma unroll 17
        for (int k = 0; k < 34; ++k) {         // 34*256 = 8704 = 136 pix * 64 ch
            int i = t + k*256;
            int pix = i % 136, ch = i / 136;
            int sc = pix % 34, sr = pix / 34;
            int R  = y0 + sr;                   // padded row
            float v = 0.0f;
            if (R >= 1 && R <= HH && sc >= 1 && sc <= WW)
                v = x[((b*CIN + ch)*HH + (R - 1))*WW + (sc - 1)];
            halo[pix*HSTR + ch] = v;
            mx = max(mx, __float_as_uint(fabsf(v)));
        }
        #pragma unroll
        for (int o = 16; o; o >>= 1) mx = max(mx, __shfl_xor_sync(0xffffffffu, mx, o));
        if (lane == 0) sredx[wid] = mx;
        GBAR(1, 256);
        if (t < 32) {
            unsigned m2 = (lane < 8) ? sredx[lane] : 0u;
            #pragma unroll
            for (int o = 4; o; o >>= 1) m2 = max(m2, __shfl_xor_sync(0xffffffffu, m2, o));
            if (t == 0) {
                g_partx[bx] = m2;
                bar_arrive_wait(&g_barX);
            }
        }
        GBAR(1, 256);
        if (t < 32) {
            unsigned vx = max(max(g_partx[lane], g_partx[lane + 32]),
                              max(g_partx[lane + 64], g_partx[lane + 96]));
            #pragma unroll
            for (int o = 16; o; o >>= 1) vx = max(vx, __shfl_xor_sync(0xffffffffu, vx, o));
            if (t == 0) {
                float Tf = __fadd_rn(__fmul_rn(0.95f, Tf_in[0]),
                                     __fmul_rn(0.05f, __uint_as_float(vx)));
                s_T[0] = Tf;
                s_sc[0] = __fdiv_rn(127.0f, Tf);
            }
        }
        GBAR(1, 256);
        // quantize halo -> int8 staging (544 items over 256 threads)
        {
            const float sf = s_sc[0];
            #pragma unroll
            for (int k = 0; k < 3; ++k) {
                int i = t + k*256;
                if (i < 544) {
                    int pix = i >> 2, c4 = i & 3;
                    const float* hp = halo + pix*HSTR + c4*16;
                    int q[16];
                    #pragma unroll
                    for (int j = 0; j < 16; ++j)
                        q[j] = quant(hp[j], sf) & 255;
                    int4 v;
                    v.x = q[0]  | (q[1]  << 8) | (q[2]  << 16) | (q[3]  << 24);
                    v.y = q[4]  | (q[5]  << 8) | (q[6]  << 16) | (q[7]  << 24);
                    v.z = q[8]  | (q[9]  << 8) | (q[10] << 16) | (q[11] << 24);
                    v.w = q[12] | (q[13] << 8) | (q[14] << 16) | (q[15] << 24);
                    *(int4*)(sm + STAGE + pix*PIXSTR + c4*16) = v;
                }
            }
        }
    } else {
        // ================= w-path: warps 8-15 (256 threads) =================
        const int tw = t - 256;
        unsigned mw;
        {
            float wv0 = w[bx*576 + tw];
            float wv1 = w[bx*576 + 256 + tw];
            wrow[tw] = wv0;
            wrow[256 + tw] = wv1;
            mw = max(__float_as_uint(fabsf(wv0)), __float_as_uint(fabsf(wv1)));
            if (tw < 64) {
                float wv2 = w[bx*576 + 512 + tw];
                wrow[512 + tw] = wv2;
                mw = max(mw, __float_as_uint(fabsf(wv2)));
            }
        }
        #pragma unroll
        for (int o = 16; o; o >>= 1) mw = max(mw, __shfl_xor_sync(0xffffffffu, mw, o));
        if (lane == 0) sredw[wid - 8] = mw;
        GBAR(2, 256);
        if (tw < 32) {
            unsigned m2 = (lane < 8) ? sredw[lane] : 0u;
            #pragma unroll
            for (int o = 4; o; o >>= 1) m2 = max(m2, __shfl_xor_sync(0xffffffffu, m2, o));
            if (tw == 0) {
                g_partw[bx] = m2;
                bar_arrive_wait(&g_barW);
            }
        }
        GBAR(2, 256);
        if (tw < 32) {
            unsigned vw = max(max(g_partw[lane], g_partw[lane + 32]),
                              max(g_partw[lane + 64], g_partw[lane + 96]));
            #pragma unroll
            for (int o = 16; o; o >>= 1) vw = max(vw, __shfl_xor_sync(0xffffffffu, vw, o));
            if (tw == 0) {
                float Tw = __fadd_rn(__fmul_rn(0.95f, Tw_in[0]),
                                     __fmul_rn(0.05f, __uint_as_float(vw)));
                s_T[1] = Tw;
                s_sc[1] = __fdiv_rn(127.0f, Tw);
            }
        }
        GBAR(2, 256);
        if (tw < 144) {
            const int tap = tw >> 4, c4w = tw & 15;
            const float sf = s_sc[1];
            int q0 = quant(wrow[(c4w*4 + 0)*9 + tap], sf) & 255;
            int q1 = quant(wrow[(c4w*4 + 1)*9 + tap], sf) & 255;
            int q2 = quant(wrow[(c4w*4 + 2)*9 + tap], sf) & 255;
            int q3 = quant(wrow[(c4w*4 + 3)*9 + tap], sf) & 255;
            g_wpack[bx*144 + tw] = q0 | (q1 << 8) | (q2 << 16) | (q3 << 24);
        }
        GBAR(2, 256);
        if (tw == 0) bar_arrive_wait(&g_barB);
        GBAR(2, 256);
        // B-fill: [co][576B] stride 592 (4608 int4 over 256 threads)
        {
            const int4* __restrict__ src = (const int4*)g_wpack;
            int4* __restrict__ Bm = (int4*)(sm + BOFF);
            #pragma unroll
            for (int k = 0; k < 18; ++k) {
                int i = tw + k*256;
                int co = i / 36, j = i % 36;
                Bm[co*37 + j] = src[i];
            }
        }
    }
    __syncthreads();
    if (t == 0)
        s_sc[2] = __fmul_rn(__fdiv_rn(s_T[0], 127.0f), __fdiv_rn(s_T[1], 127.0f));
    __syncthreads();

    // ===== hybrid mainloop: warps 0-11 IMMA (co 0..95), warps 12-15 dp4a (co 96..127) =====
    const uint32_t sbase = smem_u32(sm);
    const float sc = s_sc[2];

    if (wid < 12) {
        // ---- IMMA: 12 warps = 4(M) x 3(N); warp = m16 x n32 ----
        const int wm = (wid & 3) * 16;
        const int wn = (wid >> 2) * 32;

        const int pix = wm + (lane & 15);
        const uint32_t aAddr0 = sbase + STAGE
                              + (uint32_t)(((pix >> 5)*34 + (pix & 31))*PIXSTR)
                              + (uint32_t)(lane >> 4)*16;
        uint32_t bAddr[2];
        #pragma unroll
        for (int np = 0; np < 2; ++np)
            bAddr[np] = sbase + BOFF
                      + (uint32_t)(wn + np*16 + (lane & 7) + ((lane >> 4) & 1)*8)*BROW
                      + (uint32_t)((lane >> 3) & 1)*16;

        int acc[4][4];
        #pragma unroll
        for (int nf = 0; nf < 4; ++nf)
            #pragma unroll
            for (int j = 0; j < 4; ++j) acc[nf][j] = 0;

        #pragma unroll
        for (int ks = 0; ks < 18; ++ks) {
            const int tap = ks >> 1;
            const uint32_t aoff = (uint32_t)(((tap/3)*34 + (tap%3))*PIXSTR + (ks & 1)*32);
            const uint32_t boff = (uint32_t)ks * 32;
            uint32_t a[4], bb[2][4];
            LDSM_X4(a[0], a[1], a[2], a[3], aAddr0 + aoff);
            #pragma unroll
            for (int np = 0; np < 2; ++np)
                LDSM_X4(bb[np][0], bb[np][1], bb[np][2], bb[np][3], bAddr[np] + boff);
            #pragma unroll
            for (int nf = 0; nf < 4; ++nf)
                IMMA(acc[nf], a[0], a[1], a[2], a[3],
                     bb[nf >> 1][(nf & 1)*2], bb[nf >> 1][(nf & 1)*2 + 1]);
        }

        // epilogue
        const int p0 = wm + (lane >> 2);
        #pragma unroll
        for (int nf = 0; nf < 4; ++nf) {
            const int co0 = wn + nf*8 + (lane & 3)*2;
            const float b0 = __ldg(&bias[co0]);
            const float b1 = __ldg(&bias[co0 + 1]);
            #pragma unroll
            for (int half = 0; half < 2; ++half) {
                const int p = p0 + half*8;
                const int y = y0 + (p >> 5), xx = p & 31;
                float* po = out + (((size_t)b*COUT + co0)*HH + y)*WW + xx;
                po[0]     = (float)acc[nf][half*2]     * sc + b0;
                po[HH*WW] = (float)acc[nf][half*2 + 1] * sc + b1;
            }
        }
    } else {
        // ---- dp4a: 4 warps; thread = 1 pixel x 16 couts (co 96..127) ----
        const int dw  = wid - 12;
        const int pix = (dw & 1)*32 + lane;                 // 0..63
        const int cb  = 96 + (dw >> 1)*16;                  // 96 or 112
        const char* aBase = sm + STAGE + (size_t)(((pix >> 5)*34 + (pix & 31))*PIXSTR);
        const char* bBase = sm + BOFF + (size_t)cb*BROW;

        int acc[16];
        #pragma unroll
        for (int co = 0; co < 16; ++co) acc[co] = 0;

        #pragma unroll 1
        for (int tap = 0; tap < 9; ++tap) {
            const char* ap = aBase + ((tap/3)*34 + (tap%3))*PIXSTR;
            const char* bp = bBase + tap*64;
            #pragma unroll
            for (int c4 = 0; c4 < 4; ++c4) {
                int4 xv = *(const int4*)(ap + c4*16);
                #pragma unroll
                for (int co = 0; co < 16; ++co) {
                    int4 wv = *(const int4*)(bp + co*BROW + c4*16);
                    acc[co] = __dp4a(xv.x, wv.x, acc[co]);
                    acc[co] = __dp4a(xv.y, wv.y, acc[co]);
                    acc[co] = __dp4a(xv.z, wv.z, acc[co]);
                    acc[co] = __dp4a(xv.w, wv.w, acc[co]);
                }
            }
        }

        // epilogue: coalesced per-co row stores (lanes = consecutive x)
        const int y = y0 + (pix >> 5), xx = pix & 31;
        float* po = out + (((size_t)b*COUT + cb)*HH + y)*WW + xx;
        #pragma unroll
        for (int co = 0; co < 16; ++co)
            po[(size_t)co*HH*WW] = (float)acc[co] * sc + __ldg(&bias[cb + co]);
    }
}

// ---------------- launch ----------------
extern "C" void kernel_launch(void* const* d_in, const int* in_sizes, int n_in,
                              void* d_out, int out_size) {
    const float* x    = (const float*)d_in[0];
    const float* w    = (const float*)d_in[1];
    const float* bias = (const float*)d_in[2];
    // d_in[3] = lut (exact a*b -> tensor/dp4a), d_in[4] = gradient_lut (unused)
    const float* Tf   = (const float*)d_in[5];
    const float* Tw   = (const float*)d_in[6];
    float* out = (float*)d_out;

    cudaFuncSetAttribute(k_fused, cudaFuncAttributeMaxDynamicSharedMemorySize, SMEM_SZ);
    k_fused<<<NCTA, NTHR, SMEM_SZ>>>(x, w, bias, Tf, Tw, out);
}

// round 15
// speedup vs baseline: 1.4810x; 1.0346x over previous
#include <cuda_runtime.h>
#include <cstdint>

#define NB   8
#define CIN  64
#define COUT 128
#define HH   32
#define WW   32
#define QWN  (COUT*144)            // 18432 int32 words of packed B

#define BROW   592                 // 576+16 pad (37*16B, odd) -> conflict-free ldmatrix
#define BOFF   0
#define BSZ    (COUT*BROW)         // 75776
#define HALO   BSZ                 // float halo: 136 pixels x 65 floats (odd stride)
#define HSTR   65
#define STAGE  (HALO + 136*HSTR*4) // 111136: int8 staging, 136 pixels x 80B
#define PIXSTR 80
#define STI4   (136*PIXSTR/16)     // 680 int4 staging words
#define WROW   (STAGE + 136*PIXSTR)// 122016: w-row floats (576)
#define SMEM_SZ (WROW + 576*4)     // 124320

#define NCTA 128
#define NTHR 512

// ---------------- scratch (device globals; no allocation) ----------------
__device__ unsigned g_partx[NCTA];
__device__ unsigned g_partw[NCTA];
__device__ int      g_wpack[QWN];         // [co][tap][c4w]; CTA bx packs row co=bx
__device__ unsigned g_barX = 0u;          // monotonic grid-barrier counters
__device__ unsigned g_barW = 0u;
__device__ unsigned g_barB = 0u;

__device__ __forceinline__ uint32_t smem_u32(const void* p) {
    uint32_t a;
    asm("{ .reg .u64 t; cvta.to.shared.u64 t, %1; cvt.u32.u64 %0, t; }" : "=r"(a) : "l"(p));
    return a;
}

#define LDSM_X4(r0, r1, r2, r3, a) \
    asm volatile("ldmatrix.sync.aligned.m8n8.x4.shared.b16 {%0,%1,%2,%3}, [%4];" \
                 : "=r"(r0), "=r"(r1), "=r"(r2), "=r"(r3) : "r"(a))

#define IMMA(c, a0, a1, a2, a3, b0, b1) \
    asm volatile("mma.sync.aligned.m16n8k32.row.col.s32.s8.s8.s32 " \
                 "{%0,%1,%2,%3}, {%4,%5,%6,%7}, {%8,%9}, {%0,%1,%2,%3};" \
                 : "+r"((c)[0]), "+r"((c)[1]), "+r"((c)[2]), "+r"((c)[3]) \
                 : "r"(a0), "r"(a1), "r"(a2), "r"(a3), "r"(b0), "r"(b1))

#define GBAR(id, n) asm volatile("bar.sync %0, %1;" :: "r"(id), "r"(n) : "memory")

__device__ __forceinline__ int quant(float v, float s) {
    float r = rintf(__fmul_rn(v, s));      // round half-to-even == jnp.round
    r = fminf(fmaxf(r, -128.0f), 127.0f);
    return (int)r;
}

// single-thread arrive+wait on a monotonic 128-CTA barrier (all CTAs co-resident)
__device__ __forceinline__ void bar_arrive_wait(unsigned* bar) {
    __threadfence();
    unsigned ticket = atomicAdd(bar, 1u);
    unsigned target = (ticket & ~127u) + 128u;
    unsigned v;
    do {
        asm volatile("ld.acquire.gpu.u32 %0, [%1];" : "=r"(v) : "l"(bar) : "memory");
    } while ((int)(v - target) < 0);
}

// ---------------- ONE fused kernel, dual warp-specialized pipelines ----------------
__global__ void __launch_bounds__(NTHR, 1)
k_fused(const float* __restrict__ x, const float* __restrict__ w,
        const float* __restrict__ bias,
        const float* __restrict__ Tf_in, const float* __restrict__ Tw_in,
        float* __restrict__ out) {
    extern __shared__ char sm[];
    __shared__ unsigned sredx[8], sredw[8];
    __shared__ float s_sc[3], s_T[2];

    const int t = threadIdx.x, wid = t >> 5, lane = t & 31;
    const int bx = blockIdx.x;
    const int b  = bx >> 4;
    const int y0 = (bx & 15) * 2;

    float* __restrict__ halo = (float*)(sm + HALO);
    float* __restrict__ wrow = (float*)(sm + WROW);

    if (wid < 8) {
        // ================= x-path: warps 0-7 (256 threads) =================
        // zero int8 staging (covers padding pixels); overlaps with halo loads below
        {
            int4 z = make_int4(0, 0, 0, 0);
            int4* sz = (int4*)(sm + STAGE);
            #pragma unroll
            for (int k = 0; k < 3; ++k) {
                int i = t + k*256;
                if (i < STI4) sz[i] = z;
            }
        }
        // coalesced halo load: task j = (row4, ch); lane = col (one 128B line/iter)
        unsigned mx = 0u;
        #pragma unroll 16
        for (int j = wid; j < 256; j += 8) {
            int ch = j & 63, r4 = j >> 6;
            int R = y0 + r4;
            if (R >= 1 && R <= HH) {
                float v = x[((b*CIN + ch)*HH + (R - 1))*WW + lane];
                halo[(r4*34 + lane + 1)*HSTR + ch] = v;   // stride-65 words: conflict-free
                mx = max(mx, __float_as_uint(fabsf(v)));
            }
        }
        #pragma unroll
        for (int o = 16; o; o >>= 1) mx = max(mx, __shfl_xor_sync(0xffffffffu, mx, o));
        if (lane == 0) sredx[wid] = mx;
        GBAR(1, 256);
        if (t < 32) {
            unsigned m2 = (lane < 8) ? sredx[lane] : 0u;
            #pragma unroll
            for (int o = 4; o; o >>= 1) m2 = max(m2, __shfl_xor_sync(0xffffffffu, m2, o));
            if (t == 0) {
                g_partx[bx] = m2;
                bar_arrive_wait(&g_barX);
            }
        }
        GBAR(1, 256);
        if (t < 32) {
            unsigned vx = max(max(g_partx[lane], g_partx[lane + 32]),
                              max(g_partx[lane + 64], g_partx[lane + 96]));
            #pragma unroll
            for (int o = 16; o; o >>= 1) vx = max(vx, __shfl_xor_sync(0xffffffffu, vx, o));
            if (t == 0) {
                float Tf = __fadd_rn(__fmul_rn(0.95f, Tf_in[0]),
                                     __fmul_rn(0.05f, __uint_as_float(vx)));
                s_T[0] = Tf;
                s_sc[0] = __fdiv_rn(127.0f, Tf);
            }
        }
        GBAR(1, 256);
        // quantize VALID pixels only -> int8 staging (512 items, pow-2 indexing)
        {
            const float sf = s_sc[0];
            #pragma unroll
            for (int k = 0; k < 2; ++k) {
                int i = t + k*256;                 // 0..511
                int c4 = i & 3, p = i >> 2;        // p: 0..127
                int col = (p & 31) + 1, sr = p >> 5;
                int R = y0 + sr;
                if (R >= 1 && R <= HH) {
                    int pix = sr*34 + col;
                    const float* hp = halo + pix*HSTR + c4*16;
                    int q[16];
                    #pragma unroll
                    for (int j = 0; j < 16; ++j)
                        q[j] = quant(hp[j], sf) & 255;
                    int4 v;
                    v.x = q[0]  | (q[1]  << 8) | (q[2]  << 16) | (q[3]  << 24);
                    v.y = q[4]  | (q[5]  << 8) | (q[6]  << 16) | (q[7]  << 24);
                    v.z = q[8]  | (q[9]  << 8) | (q[10] << 16) | (q[11] << 24);
                    v.w = q[12] | (q[13] << 8) | (q[14] << 16) | (q[15] << 24);
                    *(int4*)(sm + STAGE + pix*PIXSTR + c4*16) = v;
                }
            }
        }
    } else {
        // ================= w-path: warps 8-15 (256 threads) =================
        const int tw = t - 256;
        unsigned mw;
        {
            float wv0 = w[bx*576 + tw];
            float wv1 = w[bx*576 + 256 + tw];
            wrow[tw] = wv0;
            wrow[256 + tw] = wv1;
            mw = max(__float_as_uint(fabsf(wv0)), __float_as_uint(fabsf(wv1)));
            if (tw < 64) {
                float wv2 = w[bx*576 + 512 + tw];
                wrow[512 + tw] = wv2;
                mw = max(mw, __float_as_uint(fabsf(wv2)));
            }
        }
        #pragma unroll
        for (int o = 16; o; o >>= 1) mw = max(mw, __shfl_xor_sync(0xffffffffu, mw, o));
        if (lane == 0) sredw[wid - 8] = mw;
        GBAR(2, 256);
        if (tw < 32) {
            unsigned m2 = (lane < 8) ? sredw[lane] : 0u;
            #pragma unroll
            for (int o = 4; o; o >>= 1) m2 = max(m2, __shfl_xor_sync(0xffffffffu, m2, o));
            if (tw == 0) {
                g_partw[bx] = m2;
                bar_arrive_wait(&g_barW);
            }
        }
        GBAR(2, 256);
        if (tw < 32) {
            unsigned vw = max(max(g_partw[lane], g_partw[lane + 32]),
                              max(g_partw[lane + 64], g_partw[lane + 96]));
            #pragma unroll
            for (int o = 16; o; o >>= 1) vw = max(vw, __shfl_xor_sync(0xffffffffu, vw, o));
            if (tw == 0) {
                float Tw = __fadd_rn(__fmul_rn(0.95f, Tw_in[0]),
                                     __fmul_rn(0.05f, __uint_as_float(vw)));
                s_T[1] = Tw;
                s_sc[1] = __fdiv_rn(127.0f, Tw);
            }
        }
        GBAR(2, 256);
        if (tw < 144) {
            const int tap = tw >> 4, c4w = tw & 15;
            const float sf = s_sc[1];
            int q0 = quant(wrow[(c4w*4 + 0)*9 + tap], sf) & 255;
            int q1 = quant(wrow[(c4w*4 + 1)*9 + tap], sf) & 255;
            int q2 = quant(wrow[(c4w*4 + 2)*9 + tap], sf) & 255;
            int q3 = quant(wrow[(c4w*4 + 3)*9 + tap], sf) & 255;
            g_wpack[bx*144 + tw] = q0 | (q1 << 8) | (q2 << 16) | (q3 << 24);
        }
        GBAR(2, 256);
        if (tw == 0) bar_arrive_wait(&g_barB);
        GBAR(2, 256);
        // B-fill: [co][576B] stride 592 (4608 int4 over 256 threads)
        {
            const int4* __restrict__ src = (const int4*)g_wpack;
            int4* __restrict__ Bm = (int4*)(sm + BOFF);
            #pragma unroll
            for (int k = 0; k < 18; ++k) {
                int i = tw + k*256;
                int co = i / 36, j = i % 36;
                Bm[co*37 + j] = src[i];
            }
        }
    }
    __syncthreads();
    if (t == 0)
        s_sc[2] = __fmul_rn(__fdiv_rn(s_T[0], 127.0f), __fdiv_rn(s_T[1], 127.0f));
    __syncthreads();

    // ===== hybrid mainloop: warps 0-11 IMMA (co 0..95), warps 12-15 dp4a (co 96..127) =====
    const uint32_t sbase = smem_u32(sm);
    const float sc = s_sc[2];

    if (wid < 12) {
        // ---- IMMA: 12 warps = 4(M) x 3(N); warp = m16 x n32 ----
        const int wm = (wid & 3) * 16;
        const int wn = (wid >> 2) * 32;

        const int pix = wm + (lane & 15);
        const uint32_t aAddr0 = sbase + STAGE
                              + (uint32_t)(((pix >> 5)*34 + (pix & 31))*PIXSTR)
                              + (uint32_t)(lane >> 4)*16;
        uint32_t bAddr[2];
        #pragma unroll
        for (int np = 0; np < 2; ++np)
            bAddr[np] = sbase + BOFF
                      + (uint32_t)(wn + np*16 + (lane & 7) + ((lane >> 4) & 1)*8)*BROW
                      + (uint32_t)((lane >> 3) & 1)*16;

        int acc[4][4];
        #pragma unroll
        for (int nf = 0; nf < 4; ++nf)
            #pragma unroll
            for (int j = 0; j < 4; ++j) acc[nf][j] = 0;

        #pragma unroll
        for (int ks = 0; ks < 18; ++ks) {
            const int tap = ks >> 1;
            const uint32_t aoff = (uint32_t)(((tap/3)*34 + (tap%3))*PIXSTR + (ks & 1)*32);
            const uint32_t boff = (uint32_t)ks * 32;
            uint32_t a[4], bb[2][4];
            LDSM_X4(a[0], a[1], a[2], a[3], aAddr0 + aoff);
            #pragma unroll
            for (int np = 0; np < 2; ++np)
                LDSM_X4(bb[np][0], bb[np][1], bb[np][2], bb[np][3], bAddr[np] + boff);
            #pragma unroll
            for (int nf = 0; nf < 4; ++nf)
                IMMA(acc[nf], a[0], a[1], a[2], a[3],
                     bb[nf >> 1][(nf & 1)*2], bb[nf >> 1][(nf & 1)*2 + 1]);
        }

        // epilogue
        const int p0 = wm + (lane >> 2);
        #pragma unroll
        for (int nf = 0; nf < 4; ++nf) {
            const int co0 = wn + nf*8 + (lane & 3)*2;
            const float b0 = __ldg(&bias[co0]);
            const float b1 = __ldg(&bias[co0 + 1]);
            #pragma unroll
            for (int half = 0; half < 2; ++half) {
                const int p = p0 + half*8;
                const int y = y0 + (p >> 5), xx = p & 31;
                float* po = out + (((size_t)b*COUT + co0)*HH + y)*WW + xx;
                po[0]     = (float)acc[nf][half*2]     * sc + b0;
                po[HH*WW] = (float)acc[nf][half*2 + 1] * sc + b1;
            }
        }
    } else {
        // ---- dp4a: 4 warps; thread = 2 pixels x 8 couts (co 96..127) ----
        const int g  = wid - 12;                 // 0..3 -> cout group
        const int cb = 96 + g*8;
        const char* aB0 = sm + STAGE + (size_t)(lane*PIXSTR);          // row y0, col=lane
        const char* aB1 = sm + STAGE + (size_t)((34 + lane)*PIXSTR);   // row y0+1
        const char* bB  = sm + BOFF + (size_t)cb*BROW;

        int acc[2][8];
        #pragma unroll
        for (int r = 0; r < 2; ++r)
            #pragma unroll
            for (int co = 0; co < 8; ++co) acc[r][co] = 0;

        #pragma unroll 1
        for (int tap = 0; tap < 9; ++tap) {
            const int toff = ((tap/3)*34 + (tap%3))*PIXSTR;
            const char* bp = bB + tap*64;
            #pragma unroll
            for (int c4 = 0; c4 < 4; ++c4) {
                int4 x0 = *(const int4*)(aB0 + toff + c4*16);
                int4 x1 = *(const int4*)(aB1 + toff + c4*16);
                #pragma unroll
                for (int co = 0; co < 8; ++co) {
                    int4 wv = *(const int4*)(bp + co*BROW + c4*16);
                    acc[0][co] = __dp4a(x0.x, wv.x, acc[0][co]);
                    acc[0][co] = __dp4a(x0.y, wv.y, acc[0][co]);
                    acc[0][co] = __dp4a(x0.z, wv.z, acc[0][co]);
                    acc[0][co] = __dp4a(x0.w, wv.w, acc[0][co]);
                    acc[1][co] = __dp4a(x1.x, wv.x, acc[1][co]);
                    acc[1][co] = __dp4a(x1.y, wv.y, acc[1][co]);
                    acc[1][co] = __dp4a(x1.z, wv.z, acc[1][co]);
                    acc[1][co] = __dp4a(x1.w, wv.w, acc[1][co]);
                }
            }
        }

        // epilogue: coalesced per-co row stores (lanes = consecutive x)
        #pragma unroll
        for (int r = 0; r < 2; ++r) {
            const int y = y0 + r;
            float* po = out + (((size_t)b*COUT + cb)*HH + y)*WW + lane;
            #pragma unroll
            for (int co = 0; co < 8; ++co)
                po[(size_t)co*HH*WW] = (float)acc[r][co] * sc + __ldg(&bias[cb + co]);
        }
    }
}

// ---------------- launch ----------------
extern "C" void kernel_launch(void* const* d_in, const int* in_sizes, int n_in,
                              void* d_out, int out_size) {
    const float* x    = (const float*)d_in[0];
    const float* w    = (const float*)d_in[1];
    const float* bias = (const float*)d_in[2];
    // d_in[3] = lut (exact a*b -> tensor/dp4a), d_in[4] = gradient_lut (unused)
    const float* Tf   = (const float*)d_in[5];
    const float* Tw   = (const float*)d_in[6];
    float* out = (float*)d_out;

    cudaFuncSetAttribute(k_fused, cudaFuncAttributeMaxDynamicSharedMemorySize, SMEM_SZ);
    k_fused<<<NCTA, NTHR, SMEM_SZ>>>(x, w, bias, Tf, Tw, out);
}

// round 16
// speedup vs baseline: 1.6212x; 1.0947x over previous
#include <cuda_runtime.h>
#include <cstdint>

#define NB   8
#define CIN  64
#define COUT 128
#define HH   32
#define WW   32
#define QWN  (COUT*144)            // 18432 int32 words of packed B

#define BROW   592                 // 576+16 pad (37*16B, odd) -> conflict-free ldmatrix
#define BOFF   0
#define BSZ    (COUT*BROW)         // 75776
#define HALO   BSZ                 // float halo: 136 pixels x 65 floats (odd stride)
#define HSTR   65
#define STAGE  (HALO + 136*HSTR*4) // 111136: int8 staging, 136 pixels x 80B
#define PIXSTR 80
#define STI4   (136*PIXSTR/16)     // 680 int4 staging words
#define WROW   (STAGE + 136*PIXSTR)// 122016: w-row floats (576)
#define SMEM_SZ (WROW + 576*4)     // 124320

#define NCTA 128
#define NTHR 512

// mainloop split: IMMA couts [0,72), dp4a couts [72,128)
#define CO_IMMA 72
#define NDP     14                 // couts per dp4a warp

// ---------------- scratch (device globals; no allocation) ----------------
__device__ unsigned g_partx[NCTA];
__device__ unsigned g_partw[NCTA];
__device__ int      g_wpack[QWN];         // [co][tap][c4w]; CTA bx packs row co=bx
__device__ unsigned g_barX = 0u;          // monotonic grid-barrier counters
__device__ unsigned g_barW = 0u;
__device__ unsigned g_barB = 0u;

__device__ __forceinline__ uint32_t smem_u32(const void* p) {
    uint32_t a;
    asm("{ .reg .u64 t; cvta.to.shared.u64 t, %1; cvt.u32.u64 %0, t; }" : "=r"(a) : "l"(p));
    return a;
}

#define LDSM_X4(r0, r1, r2, r3, a) \
    asm volatile("ldmatrix.sync.aligned.m8n8.x4.shared.b16 {%0,%1,%2,%3}, [%4];" \
                 : "=r"(r0), "=r"(r1), "=r"(r2), "=r"(r3) : "r"(a))

#define IMMA(c, a0, a1, a2, a3, b0, b1) \
    asm volatile("mma.sync.aligned.m16n8k32.row.col.s32.s8.s8.s32 " \
                 "{%0,%1,%2,%3}, {%4,%5,%6,%7}, {%8,%9}, {%0,%1,%2,%3};" \
                 : "+r"((c)[0]), "+r"((c)[1]), "+r"((c)[2]), "+r"((c)[3]) \
                 : "r"(a0), "r"(a1), "r"(a2), "r"(a3), "r"(b0), "r"(b1))

#define GBAR(id, n) asm volatile("bar.sync %0, %1;" :: "r"(id), "r"(n) : "memory")

__device__ __forceinline__ int quant(float v, float s) {
    float r = rintf(__fmul_rn(v, s));      // round half-to-even == jnp.round
    r = fminf(fmaxf(r, -128.0f), 127.0f);
    return (int)r;
}

// single-thread arrive+wait on a monotonic 128-CTA barrier (all CTAs co-resident)
__device__ __forceinline__ void bar_arrive_wait(unsigned* bar) {
    __threadfence();
    unsigned ticket = atomicAdd(bar, 1u);
    unsigned target = (ticket & ~127u) + 128u;
    unsigned v;
    do {
        asm volatile("ld.acquire.gpu.u32 %0, [%1];" : "=r"(v) : "l"(bar) : "memory");
    } while ((int)(v - target) < 0);
}

// ---------------- ONE fused kernel, dual warp-specialized pipelines ----------------
__global__ void __launch_bounds__(NTHR, 1)
k_fused(const float* __restrict__ x, const float* __restrict__ w,
        const float* __restrict__ bias,
        const float* __restrict__ Tf_in, const float* __restrict__ Tw_in,
        float* __restrict__ out) {
    extern __shared__ char sm[];
    __shared__ unsigned sredx[8], sredw[8];
    __shared__ float s_sc[3], s_T[2];

    const int t = threadIdx.x, wid = t >> 5, lane = t & 31;
    const int bx = blockIdx.x;
    const int b  = bx >> 4;
    const int y0 = (bx & 15) * 2;

    float* __restrict__ halo = (float*)(sm + HALO);
    float* __restrict__ wrow = (float*)(sm + WROW);

    if (wid < 8) {
        // ================= x-path: warps 0-7 (256 threads) =================
        // zero int8 staging (covers padding pixels)
        {
            int4 z = make_int4(0, 0, 0, 0);
            int4* sz = (int4*)(sm + STAGE);
            #pragma unroll
            for (int k = 0; k < 3; ++k) {
                int i = t + k*256;
                if (i < STI4) sz[i] = z;
            }
        }
        // coalesced halo load: task j = (row4, ch); lane = col (one 128B line/iter)
        unsigned mx = 0u;
        #pragma unroll 16
        for (int j = wid; j < 256; j += 8) {
            int ch = j & 63, r4 = j >> 6;
            int R = y0 + r4;
            if (R >= 1 && R <= HH) {
                float v = x[((b*CIN + ch)*HH + (R - 1))*WW + lane];
                halo[(r4*34 + lane + 1)*HSTR + ch] = v;   // stride-65 words: conflict-free
                mx = max(mx, __float_as_uint(fabsf(v)));
            }
        }
        #pragma unroll
        for (int o = 16; o; o >>= 1) mx = max(mx, __shfl_xor_sync(0xffffffffu, mx, o));
        if (lane == 0) sredx[wid] = mx;
        GBAR(1, 256);
        if (t < 32) {
            unsigned m2 = (lane < 8) ? sredx[lane] : 0u;
            #pragma unroll
            for (int o = 4; o; o >>= 1) m2 = max(m2, __shfl_xor_sync(0xffffffffu, m2, o));
            if (t == 0) {
                g_partx[bx] = m2;
                bar_arrive_wait(&g_barX);
            }
        }
        GBAR(1, 256);
        if (t < 32) {
            unsigned vx = max(max(g_partx[lane], g_partx[lane + 32]),
                              max(g_partx[lane + 64], g_partx[lane + 96]));
            #pragma unroll
            for (int o = 16; o; o >>= 1) vx = max(vx, __shfl_xor_sync(0xffffffffu, vx, o));
            if (t == 0) {
                float Tf = __fadd_rn(__fmul_rn(0.95f, Tf_in[0]),
                                     __fmul_rn(0.05f, __uint_as_float(vx)));
                s_T[0] = Tf;
                s_sc[0] = __fdiv_rn(127.0f, Tf);
            }
        }
        GBAR(1, 256);
        // quantize VALID pixels only -> int8 staging (512 items, pow-2 indexing)
        {
            const float sf = s_sc[0];
            #pragma unroll
            for (int k = 0; k < 2; ++k) {
                int i = t + k*256;                 // 0..511
                int c4 = i & 3, p = i >> 2;        // p: 0..127
                int col = (p & 31) + 1, sr = p >> 5;
                int R = y0 + sr;
                if (R >= 1 && R <= HH) {
                    int pix = sr*34 + col;
                    const float* hp = halo + pix*HSTR + c4*16;
                    int q[16];
                    #pragma unroll
                    for (int j = 0; j < 16; ++j)
                        q[j] = quant(hp[j], sf) & 255;
                    int4 v;
                    v.x = q[0]  | (q[1]  << 8) | (q[2]  << 16) | (q[3]  << 24);
                    v.y = q[4]  | (q[5]  << 8) | (q[6]  << 16) | (q[7]  << 24);
                    v.z = q[8]  | (q[9]  << 8) | (q[10] << 16) | (q[11] << 24);
                    v.w = q[12] | (q[13] << 8) | (q[14] << 16) | (q[15] << 24);
                    *(int4*)(sm + STAGE + pix*PIXSTR + c4*16) = v;
                }
            }
        }
    } else {
        // ================= w-path: warps 8-15 (256 threads) =================
        const int tw = t - 256;
        unsigned mw;
        {
            float wv0 = w[bx*576 + tw];
            float wv1 = w[bx*576 + 256 + tw];
            wrow[tw] = wv0;
            wrow[256 + tw] = wv1;
            mw = max(__float_as_uint(fabsf(wv0)), __float_as_uint(fabsf(wv1)));
            if (tw < 64) {
                float wv2 = w[bx*576 + 512 + tw];
                wrow[512 + tw] = wv2;
                mw = max(mw, __float_as_uint(fabsf(wv2)));
            }
        }
        #pragma unroll
        for (int o = 16; o; o >>= 1) mw = max(mw, __shfl_xor_sync(0xffffffffu, mw, o));
        if (lane == 0) sredw[wid - 8] = mw;
        GBAR(2, 256);
        if (tw < 32) {
            unsigned m2 = (lane < 8) ? sredw[lane] : 0u;
            #pragma unroll
            for (int o = 4; o; o >>= 1) m2 = max(m2, __shfl_xor_sync(0xffffffffu, m2, o));
            if (tw == 0) {
                g_partw[bx] = m2;
                bar_arrive_wait(&g_barW);
            }
        }
        GBAR(2, 256);
        if (tw < 32) {
            unsigned vw = max(max(g_partw[lane], g_partw[lane + 32]),
                              max(g_partw[lane + 64], g_partw[lane + 96]));
            #pragma unroll
            for (int o = 16; o; o >>= 1) vw = max(vw, __shfl_xor_sync(0xffffffffu, vw, o));
            if (tw == 0) {
                float Tw = __fadd_rn(__fmul_rn(0.95f, Tw_in[0]),
                                     __fmul_rn(0.05f, __uint_as_float(vw)));
                s_T[1] = Tw;
                s_sc[1] = __fdiv_rn(127.0f, Tw);
            }
        }
        GBAR(2, 256);
        if (tw < 144) {
            const int tap = tw >> 4, c4w = tw & 15;
            const float sf = s_sc[1];
            int q0 = quant(wrow[(c4w*4 + 0)*9 + tap], sf) & 255;
            int q1 = quant(wrow[(c4w*4 + 1)*9 + tap], sf) & 255;
            int q2 = quant(wrow[(c4w*4 + 2)*9 + tap], sf) & 255;
            int q3 = quant(wrow[(c4w*4 + 3)*9 + tap], sf) & 255;
            g_wpack[bx*144 + tw] = q0 | (q1 << 8) | (q2 << 16) | (q3 << 24);
        }
        GBAR(2, 256);
        if (tw == 0) bar_arrive_wait(&g_barB);
        GBAR(2, 256);
        // B-fill: [co][576B] stride 592 (4608 int4 over 256 threads)
        {
            const int4* __restrict__ src = (const int4*)g_wpack;
            int4* __restrict__ Bm = (int4*)(sm + BOFF);
            #pragma unroll
            for (int k = 0; k < 18; ++k) {
                int i = tw + k*256;
                int co = i / 36, j = i % 36;
                Bm[co*37 + j] = src[i];
            }
        }
    }
    __syncthreads();
    if (t == 0)
        s_sc[2] = __fmul_rn(__fdiv_rn(s_T[0], 127.0f), __fdiv_rn(s_T[1], 127.0f));
    __syncthreads();

    // ===== hybrid mainloop: warps 0-11 IMMA (co 0..71), warps 12-15 dp4a (co 72..127) =====
    const uint32_t sbase = smem_u32(sm);
    const float sc = s_sc[2];

    if (wid < 12) {
        // ---- IMMA: 12 warps = 4(M) x 3(N); warp = m16 x n24 (3 n8 frags) ----
        const int wm = (wid & 3) * 16;
        const int wn = (wid >> 2) * 24;

        const int pix = wm + (lane & 15);
        const uint32_t aAddr0 = sbase + STAGE
                              + (uint32_t)(((pix >> 5)*34 + (pix & 31))*PIXSTR)
                              + (uint32_t)(lane >> 4)*16;
        uint32_t bAddr[2];
        #pragma unroll
        for (int np = 0; np < 2; ++np)
            bAddr[np] = sbase + BOFF
                      + (uint32_t)(wn + np*16 + (lane & 7) + ((lane >> 4) & 1)*8)*BROW
                      + (uint32_t)((lane >> 3) & 1)*16;

        int acc[3][4];
        #pragma unroll
        for (int nf = 0; nf < 3; ++nf)
            #pragma unroll
            for (int j = 0; j < 4; ++j) acc[nf][j] = 0;

        #pragma unroll
        for (int ks = 0; ks < 18; ++ks) {
            const int tap = ks >> 1;
            const uint32_t aoff = (uint32_t)(((tap/3)*34 + (tap%3))*PIXSTR + (ks & 1)*32);
            const uint32_t boff = (uint32_t)ks * 32;
            uint32_t a[4], bb[2][4];
            LDSM_X4(a[0], a[1], a[2], a[3], aAddr0 + aoff);
            #pragma unroll
            for (int np = 0; np < 2; ++np)
                LDSM_X4(bb[np][0], bb[np][1], bb[np][2], bb[np][3], bAddr[np] + boff);
            #pragma unroll
            for (int nf = 0; nf < 3; ++nf)
                IMMA(acc[nf], a[0], a[1], a[2], a[3],
                     bb[nf >> 1][(nf & 1)*2], bb[nf >> 1][(nf & 1)*2 + 1]);
        }

        // epilogue
        const int p0 = wm + (lane >> 2);
        #pragma unroll
        for (int nf = 0; nf < 3; ++nf) {
            const int co0 = wn + nf*8 + (lane & 3)*2;
            const float b0 = __ldg(&bias[co0]);
            const float b1 = __ldg(&bias[co0 + 1]);
            #pragma unroll
            for (int half = 0; half < 2; ++half) {
                const int p = p0 + half*8;
                const int y = y0 + (p >> 5), xx = p & 31;
                float* po = out + (((size_t)b*COUT + co0)*HH + y)*WW + xx;
                po[0]     = (float)acc[nf][half*2]     * sc + b0;
                po[HH*WW] = (float)acc[nf][half*2 + 1] * sc + b1;
            }
        }
    } else {
        // ---- dp4a: 4 warps; thread = 2 pixels x 14 couts (co 72..127) ----
        const int g  = wid - 12;                 // 0..3 -> cout group
        const int cb = CO_IMMA + g*NDP;          // 72, 86, 100, 114
        const char* aB0 = sm + STAGE + (size_t)(lane*PIXSTR);          // row y0, col=lane
        const char* aB1 = sm + STAGE + (size_t)((34 + lane)*PIXSTR);   // row y0+1
        const char* bB  = sm + BOFF + (size_t)cb*BROW;

        int acc[2][NDP];
        #pragma unroll
        for (int r = 0; r < 2; ++r)
            #pragma unroll
            for (int co = 0; co < NDP; ++co) acc[r][co] = 0;

        #pragma unroll 1
        for (int tap = 0; tap < 9; ++tap) {
            const int toff = ((tap/3)*34 + (tap%3))*PIXSTR;
            const char* bp = bB + tap*64;
            #pragma unroll
            for (int c4 = 0; c4 < 4; ++c4) {
                int4 x0 = *(const int4*)(aB0 + toff + c4*16);
                int4 x1 = *(const int4*)(aB1 + toff + c4*16);
                #pragma unroll
                for (int co = 0; co < NDP; ++co) {
                    int4 wv = *(const int4*)(bp + co*BROW + c4*16);
                    acc[0][co] = __dp4a(x0.x, wv.x, acc[0][co]);
                    acc[0][co] = __dp4a(x0.y, wv.y, acc[0][co]);
                    acc[0][co] = __dp4a(x0.z, wv.z, acc[0][co]);
                    acc[0][co] = __dp4a(x0.w, wv.w, acc[0][co]);
                    acc[1][co] = __dp4a(x1.x, wv.x, acc[1][co]);
                    acc[1][co] = __dp4a(x1.y, wv.y, acc[1][co]);
                    acc[1][co] = __dp4a(x1.z, wv.z, acc[1][co]);
                    acc[1][co] = __dp4a(x1.w, wv.w, acc[1][co]);
                }
            }
        }

        // epilogue: coalesced per-co row stores (lanes = consecutive x)
        #pragma unroll
        for (int r = 0; r < 2; ++r) {
            const int y = y0 + r;
            float* po = out + (((size_t)b*COUT + cb)*HH + y)*WW + lane;
            #pragma unroll
            for (int co = 0; co < NDP; ++co)
                po[(size_t)co*HH*WW] = (float)acc[r][co] * sc + __ldg(&bias[cb + co]);
        }
    }
}

// ---------------- launch ----------------
extern "C" void kernel_launch(void* const* d_in, const int* in_sizes, int n_in,
                              void* d_out, int out_size) {
    const float* x    = (const float*)d_in[0];
    const float* w    = (const float*)d_in[1];
    const float* bias = (const float*)d_in[2];
    // d_in[3] = lut (exact a*b -> tensor/dp4a), d_in[4] = gradient_lut (unused)
    const float* Tf   = (const float*)d_in[5];
    const float* Tw   = (const float*)d_in[6];
    float* out = (float*)d_out;

    cudaFuncSetAttribute(k_fused, cudaFuncAttributeMaxDynamicSharedMemorySize, SMEM_SZ);
    k_fused<<<NCTA, NTHR, SMEM_SZ>>>(x, w, bias, Tf, Tw, out);
}

// round 17
// speedup vs baseline: 1.6243x; 1.0019x over previous
#include <cuda_runtime.h>
#include <cstdint>

#define NB   8
#define CIN  64
#define COUT 128
#define HH   32
#define WW   32
#define QWN  (COUT*144)            // 18432 int32 words of packed B

#define BROW   592                 // 576+16 pad (37*16B, odd) -> conflict-free ldmatrix
#define BOFF   0
#define BSZ    (COUT*BROW)         // 75776
#define HALO   BSZ                 // float halo: 136 pixels x 65 floats (odd stride)
#define HSTR   65
#define STAGE  (HALO + 136*HSTR*4) // 111136: int8 staging, 136 pixels x 80B
#define PIXSTR 80
#define STI4   (136*PIXSTR/16)     // 680 int4 staging words
#define WROW   (STAGE + 136*PIXSTR)// 122016: w-row floats (576)
#define SMEM_SZ (WROW + 576*4)     // 124320

#define NCTA 128
#define NTHR 512

// mainloop split: IMMA couts [0,72), dp4a couts [72,128)  (discrete pareto point)
#define CO_IMMA 72
#define NDP     14                 // couts per dp4a warp

// ---------------- scratch (device globals; no allocation) ----------------
__device__ unsigned g_partx[NCTA];
__device__ unsigned g_partw[NCTA];
__device__ int      g_wpack[QWN];         // [co][tap][c4w]; CTA bx packs row co=bx
__device__ unsigned g_barX = 0u;          // monotonic grid-barrier counters
__device__ unsigned g_barW = 0u;
__device__ unsigned g_barB = 0u;

__device__ __forceinline__ uint32_t smem_u32(const void* p) {
    uint32_t a;
    asm("{ .reg .u64 t; cvta.to.shared.u64 t, %1; cvt.u32.u64 %0, t; }" : "=r"(a) : "l"(p));
    return a;
}

#define LDSM_X4(r0, r1, r2, r3, a) \
    asm volatile("ldmatrix.sync.aligned.m8n8.x4.shared.b16 {%0,%1,%2,%3}, [%4];" \
                 : "=r"(r0), "=r"(r1), "=r"(r2), "=r"(r3) : "r"(a))

#define IMMA(c, a0, a1, a2, a3, b0, b1) \
    asm volatile("mma.sync.aligned.m16n8k32.row.col.s32.s8.s8.s32 " \
                 "{%0,%1,%2,%3}, {%4,%5,%6,%7}, {%8,%9}, {%0,%1,%2,%3};" \
                 : "+r"((c)[0]), "+r"((c)[1]), "+r"((c)[2]), "+r"((c)[3]) \
                 : "r"(a0), "r"(a1), "r"(a2), "r"(a3), "r"(b0), "r"(b1))

#define GBAR(id, n) asm volatile("bar.sync %0, %1;" :: "r"(id), "r"(n) : "memory")

__device__ __forceinline__ unsigned umax4(float4 v) {
    unsigned m = __float_as_uint(fabsf(v.x));
    m = max(m, __float_as_uint(fabsf(v.y)));
    m = max(m, __float_as_uint(fabsf(v.z)));
    m = max(m, __float_as_uint(fabsf(v.w)));
    return m;
}

// round-half-even quantize: F2I.RNI then integer clamp (same semantics as
// clip(round(v*s), -128, 127) for all finite inputs in range)
__device__ __forceinline__ int quant(float v, float s) {
    int q = __float2int_rn(__fmul_rn(v, s));
    return max(-128, min(127, q));
}

// single-thread arrive+wait on a monotonic 128-CTA barrier (all CTAs co-resident)
__device__ __forceinline__ void bar_arrive_wait(unsigned* bar) {
    __threadfence();
    unsigned ticket = atomicAdd(bar, 1u);
    unsigned target = (ticket & ~127u) + 128u;
    unsigned v;
    do {
        asm volatile("ld.acquire.gpu.u32 %0, [%1];" : "=r"(v) : "l"(bar) : "memory");
    } while ((int)(v - target) < 0);
}

// ---------------- ONE fused kernel, dual warp-specialized pipelines ----------------
__global__ void __launch_bounds__(NTHR, 1)
k_fused(const float* __restrict__ x, const float* __restrict__ w,
        const float* __restrict__ bias,
        const float* __restrict__ Tf_in, const float* __restrict__ Tw_in,
        float* __restrict__ out) {
    extern __shared__ char sm[];
    __shared__ unsigned sredx[8], sredw[8];
    __shared__ float s_sc[3], s_T[2];

    const int t = threadIdx.x, wid = t >> 5, lane = t & 31;
    const int bx = blockIdx.x;
    const int b  = bx >> 4;
    const int y0 = (bx & 15) * 2;

    float* __restrict__ halo = (float*)(sm + HALO);
    float* __restrict__ wrow = (float*)(sm + WROW);

    if (wid < 8) {
        // ================= x-path: warps 0-7 (256 threads) =================
        // zero int8 staging (covers padding pixels)
        {
            int4 z = make_int4(0, 0, 0, 0);
            int4* sz = (int4*)(sm + STAGE);
            #pragma unroll
            for (int k = 0; k < 3; ++k) {
                int i = t + k*256;
                if (i < STI4) sz[i] = z;
            }
        }
        // float4 halo load: 2048 items, 8/thread, fully unrolled (max MLP)
        unsigned mx = 0u;
        {
            const float4* x4 = (const float4*)x;
            #pragma unroll
            for (int k = 0; k < 8; ++k) {
                int i = t + k*256;             // 0..2047
                int c4g = i & 7;               // float4 within row (cols 4c4g..4c4g+3)
                int ch  = (i >> 3) & 63;
                int r4  = i >> 9;              // 0..3
                int R = y0 + r4;
                if (R >= 1 && R <= HH) {
                    float4 v = x4[(((b*CIN + ch)*HH) + (R - 1))*8 + c4g];
                    int pb = (r4*34 + 4*c4g + 1)*HSTR + ch;   // banks all-distinct
                    halo[pb]       = v.x;
                    halo[pb + 65]  = v.y;
                    halo[pb + 130] = v.z;
                    halo[pb + 195] = v.w;
                    mx = max(mx, umax4(v));
                }
            }
        }
        #pragma unroll
        for (int o = 16; o; o >>= 1) mx = max(mx, __shfl_xor_sync(0xffffffffu, mx, o));
        if (lane == 0) sredx[wid] = mx;
        GBAR(1, 256);
        if (t < 32) {
            unsigned m2 = (lane < 8) ? sredx[lane] : 0u;
            #pragma unroll
            for (int o = 4; o; o >>= 1) m2 = max(m2, __shfl_xor_sync(0xffffffffu, m2, o));
            if (t == 0) {
                g_partx[bx] = m2;
                bar_arrive_wait(&g_barX);
            }
        }
        GBAR(1, 256);
        if (t < 32) {
            unsigned vx = max(max(g_partx[lane], g_partx[lane + 32]),
                              max(g_partx[lane + 64], g_partx[lane + 96]));
            #pragma unroll
            for (int o = 16; o; o >>= 1) vx = max(vx, __shfl_xor_sync(0xffffffffu, vx, o));
            if (t == 0) {
                float Tf = __fadd_rn(__fmul_rn(0.95f, Tf_in[0]),
                                     __fmul_rn(0.05f, __uint_as_float(vx)));
                s_T[0] = Tf;
                s_sc[0] = __fdiv_rn(127.0f, Tf);
            }
        }
        GBAR(1, 256);
        // quantize VALID pixels only -> int8 staging (512 items, pow-2 indexing)
        {
            const float sf = s_sc[0];
            #pragma unroll
            for (int k = 0; k < 2; ++k) {
                int i = t + k*256;                 // 0..511
                int c4 = i & 3, p = i >> 2;        // p: 0..127
                int col = (p & 31) + 1, sr = p >> 5;
                int R = y0 + sr;
                if (R >= 1 && R <= HH) {
                    int pix = sr*34 + col;
                    const float* hp = halo + pix*HSTR + c4*16;
                    int q[16];
                    #pragma unroll
                    for (int j = 0; j < 16; ++j)
                        q[j] = quant(hp[j], sf) & 255;
                    int4 v;
                    v.x = q[0]  | (q[1]  << 8) | (q[2]  << 16) | (q[3]  << 24);
                    v.y = q[4]  | (q[5]  << 8) | (q[6]  << 16) | (q[7]  << 24);
                    v.z = q[8]  | (q[9]  << 8) | (q[10] << 16) | (q[11] << 24);
                    v.w = q[12] | (q[13] << 8) | (q[14] << 16) | (q[15] << 24);
                    *(int4*)(sm + STAGE + pix*PIXSTR + c4*16) = v;
                }
            }
        }
    } else {
        // ================= w-path: warps 8-15 (256 threads) =================
        const int tw = t - 256;
        unsigned mw = 0u;
        if (tw < 144) {
            float4 v = ((const float4*)(w + (size_t)bx*576))[tw];
            ((float4*)wrow)[tw] = v;
            mw = umax4(v);
        }
        #pragma unroll
        for (int o = 16; o; o >>= 1) mw = max(mw, __shfl_xor_sync(0xffffffffu, mw, o));
        if (lane == 0) sredw[wid - 8] = mw;
        GBAR(2, 256);
        if (tw < 32) {
            unsigned m2 = (lane < 8) ? sredw[lane] : 0u;
            #pragma unroll
            for (int o = 4; o; o >>= 1) m2 = max(m2, __shfl_xor_sync(0xffffffffu, m2, o));
            if (tw == 0) {
                g_partw[bx] = m2;
                bar_arrive_wait(&g_barW);
            }
        }
        GBAR(2, 256);
        if (tw < 32) {
            unsigned vw = max(max(g_partw[lane], g_partw[lane + 32]),
                              max(g_partw[lane + 64], g_partw[lane + 96]));
            #pragma unroll
            for (int o = 16; o; o >>= 1) vw = max(vw, __shfl_xor_sync(0xffffffffu, vw, o));
            if (tw == 0) {
                float Tw = __fadd_rn(__fmul_rn(0.95f, Tw_in[0]),
                                     __fmul_rn(0.05f, __uint_as_float(vw)));
                s_T[1] = Tw;
                s_sc[1] = __fdiv_rn(127.0f, Tw);
            }
        }
        GBAR(2, 256);
        if (tw < 144) {
            const int tap = tw >> 4, c4w = tw & 15;
            const float sf = s_sc[1];
            int q0 = quant(wrow[(c4w*4 + 0)*9 + tap], sf) & 255;
            int q1 = quant(wrow[(c4w*4 + 1)*9 + tap], sf) & 255;
            int q2 = quant(wrow[(c4w*4 + 2)*9 + tap], sf) & 255;
            int q3 = quant(wrow[(c4w*4 + 3)*9 + tap], sf) & 255;
            g_wpack[bx*144 + tw] = q0 | (q1 << 8) | (q2 << 16) | (q3 << 24);
        }
        GBAR(2, 256);
        if (tw == 0) bar_arrive_wait(&g_barB);
        GBAR(2, 256);
        // B-fill: [co][576B] stride 592 (4608 int4 over 256 threads)
        {
            const int4* __restrict__ src = (const int4*)g_wpack;
            int4* __restrict__ Bm = (int4*)(sm + BOFF);
            #pragma unroll
            for (int k = 0; k < 18; ++k) {
                int i = tw + k*256;
                int co = i / 36, j = i % 36;
                Bm[co*37 + j] = src[i];
            }
        }
    }
    __syncthreads();
    if (t == 0)
        s_sc[2] = __fmul_rn(__fdiv_rn(s_T[0], 127.0f), __fdiv_rn(s_T[1], 127.0f));
    __syncthreads();

    // ===== hybrid mainloop: warps 0-11 IMMA (co 0..71), warps 12-15 dp4a (co 72..127) =====
    const uint32_t sbase = smem_u32(sm);
    const float sc = s_sc[2];

    if (wid < 12) {
        // ---- IMMA: 12 warps = 4(M) x 3(N); warp = m16 x n24 (3 n8 frags) ----
        const int wm = (wid & 3) * 16;
        const int wn = (wid >> 2) * 24;

        const int pix = wm + (lane & 15);
        const uint32_t aAddr0 = sbase + STAGE
                              + (uint32_t)(((pix >> 5)*34 + (pix & 31))*PIXSTR)
                              + (uint32_t)(lane >> 4)*16;
        uint32_t bAddr[2];
        #pragma unroll
        for (int np = 0; np < 2; ++np)
            bAddr[np] = sbase + BOFF
                      + (uint32_t)(wn + np*16 + (lane & 7) + ((lane >> 4) & 1)*8)*BROW
                      + (uint32_t)((lane >> 3) & 1)*16;

        int acc[3][4];
        #pragma unroll
        for (int nf = 0; nf < 3; ++nf)
            #pragma unroll
            for (int j = 0; j < 4; ++j) acc[nf][j] = 0;

        #pragma unroll
        for (int ks = 0; ks < 18; ++ks) {
            const int tap = ks >> 1;
            const uint32_t aoff = (uint32_t)(((tap/3)*34 + (tap%3))*PIXSTR + (ks & 1)*32);
            const uint32_t boff = (uint32_t)ks * 32;
            uint32_t a[4], bb[2][4];
            LDSM_X4(a[0], a[1], a[2], a[3], aAddr0 + aoff);
            #pragma unroll
            for (int np = 0; np < 2; ++np)
                LDSM_X4(bb[np][0], bb[np][1], bb[np][2], bb[np][3], bAddr[np] + boff);
            #pragma unroll
            for (int nf = 0; nf < 3; ++nf)
                IMMA(acc[nf], a[0], a[1], a[2], a[3],
                     bb[nf >> 1][(nf & 1)*2], bb[nf >> 1][(nf & 1)*2 + 1]);
        }

        // epilogue
        const int p0 = wm + (lane >> 2);
        #pragma unroll
        for (int nf = 0; nf < 3; ++nf) {
            const int co0 = wn + nf*8 + (lane & 3)*2;
            const float b0 = __ldg(&bias[co0]);
            const float b1 = __ldg(&bias[co0 + 1]);
            #pragma unroll
            for (int half = 0; half < 2; ++half) {
                const int p = p0 + half*8;
                const int y = y0 + (p >> 5), xx = p & 31;
                float* po = out + (((size_t)b*COUT + co0)*HH + y)*WW + xx;
                po[0]     = (float)acc[nf][half*2]     * sc + b0;
                po[HH*WW] = (float)acc[nf][half*2 + 1] * sc + b1;
            }
        }
    } else {
        // ---- dp4a: 4 warps; thread = 2 pixels x 14 couts (co 72..127) ----
        const int g  = wid - 12;                 // 0..3 -> cout group
        const int cb = CO_IMMA + g*NDP;          // 72, 86, 100, 114
        const char* aB0 = sm + STAGE + (size_t)(lane*PIXSTR);          // row y0, col=lane
        const char* aB1 = sm + STAGE + (size_t)((34 + lane)*PIXSTR);   // row y0+1
        const char* bB  = sm + BOFF + (size_t)cb*BROW;

        int acc[2][NDP];
        #pragma unroll
        for (int r = 0; r < 2; ++r)
            #pragma unroll
            for (int co = 0; co < NDP; ++co) acc[r][co] = 0;

        #pragma unroll 1
        for (int tap = 0; tap < 9; ++tap) {
            const int toff = ((tap/3)*34 + (tap%3))*PIXSTR;
            const char* bp = bB + tap*64;
            #pragma unroll
            for (int c4 = 0; c4 < 4; ++c4) {
                int4 x0 = *(const int4*)(aB0 + toff + c4*16);
                int4 x1 = *(const int4*)(aB1 + toff + c4*16);
                #pragma unroll
                for (int co = 0; co < NDP; ++co) {
                    int4 wv = *(const int4*)(bp + co*BROW + c4*16);
                    acc[0][co] = __dp4a(x0.x, wv.x, acc[0][co]);
                    acc[0][co] = __dp4a(x0.y, wv.y, acc[0][co]);
                    acc[0][co] = __dp4a(x0.z, wv.z, acc[0][co]);
                    acc[0][co] = __dp4a(x0.w, wv.w, acc[0][co]);
                    acc[1][co] = __dp4a(x1.x, wv.x, acc[1][co]);
                    acc[1][co] = __dp4a(x1.y, wv.y, acc[1][co]);
                    acc[1][co] = __dp4a(x1.z, wv.z, acc[1][co]);
                    acc[1][co] = __dp4a(x1.w, wv.w, acc[1][co]);
                }
            }
        }

        // epilogue: coalesced per-co row stores (lanes = consecutive x)
        #pragma unroll
        for (int r = 0; r < 2; ++r) {
            const int y = y0 + r;
            float* po = out + (((size_t)b*COUT + cb)*HH + y)*WW + lane;
            #pragma unroll
            for (int co = 0; co < NDP; ++co)
                po[(size_t)co*HH*WW] = (float)acc[r][co] * sc + __ldg(&bias[cb + co]);
        }
    }
}

// ---------------- launch ----------------
extern "C" void kernel_launch(void* const* d_in, const int* in_sizes, int n_in,
                              void* d_out, int out_size) {
    const float* x    = (const float*)d_in[0];
    const float* w    = (const float*)d_in[1];
    const float* bias = (const float*)d_in[2];
    // d_in[3] = lut (exact a*b -> tensor/dp4a), d_in[4] = gradient_lut (unused)
    const float* Tf   = (const float*)d_in[5];
    const float* Tw   = (const float*)d_in[6];
    float* out = (float*)d_out;

    cudaFuncSetAttribute(k_fused, cudaFuncAttributeMaxDynamicSharedMemorySize, SMEM_SZ);
    k_fused<<<NCTA, NTHR, SMEM_SZ>>>(x, w, bias, Tf, Tw, out);
}